// round 7
// baseline (speedup 1.0000x reference)
#include <cuda_runtime.h>

// out[(b*N+n)*D + c, s] = q[b, s, c] * w[n, c]
// q: (B=8, S=2048, D=256) fp32, c contiguous
// w: (N=20, D=256) fp32
// out: (B*N=160, D=256, S=2048) fp32, s contiguous
//
// R6: software-pipelined multi-tile blocks. Each block owns NT=4 s-tiles of
// 64; double-buffered smem transpose; LDG prefetch for tile t+1 overlaps the
// 40-STG.128 burst of tile t, keeping the HBM write stream near-continuous.
// 512 blocks = one resident wave.

#define BB 8
#define SS 2048
#define DD 256
#define NN 20
#define STILE 64
#define NT 4

__global__ __launch_bounds__(256)
void FeatureReweightingModule_72447508349057_kernel(
    const float* __restrict__ q,
    const float* __restrict__ w,
    float* __restrict__ out)
{
    __shared__ float tile[2][STILE][33];   // double-buffered, padded rows
    __shared__ float ws[NN][32];

    const int s_base = blockIdx.x * (STILE * NT);
    const int c0 = blockIdx.y << 5;
    const int b  = blockIdx.z;
    const int tid = threadIdx.x;           // 256 threads

    // Stage the 20x32 weight slice.
    #pragma unroll
    for (int i = tid; i < NN * 32; i += 256) {
        ws[i >> 5][i & 31] = w[(i >> 5) * DD + c0 + (i & 31)];
    }

    // Load mapping: thread covers (sl0, cq) and (sl0+32, cq), one float4 each.
    const int sl0 = tid >> 3;              // 0..31
    const int cq  = (tid & 7) << 2;        // 0,4,...,28
    const float* qbase = q + ((size_t)b * SS + s_base) * DD + c0 + cq;

    // Prologue: load tile 0 into registers, stage into buffer 0.
    float4 p0 = *reinterpret_cast<const float4*>(qbase + (size_t)sl0 * DD);
    float4 p1 = *reinterpret_cast<const float4*>(qbase + (size_t)(sl0 + 32) * DD);
    {
        float* r0 = &tile[0][sl0][cq];
        r0[0] = p0.x; r0[1] = p0.y; r0[2] = p0.z; r0[3] = p0.w;
        float* r1 = &tile[0][sl0 + 32][cq];
        r1[0] = p1.x; r1[1] = p1.y; r1[2] = p1.z; r1[3] = p1.w;
    }
    __syncthreads();

    // Store mapping: thread owns channel cl, s-quad sq (and sq+32).
    const int cl = tid >> 3;               // 0..31
    const int sq = (tid & 7) << 2;         // 0,4,...,28

    // Weights for this channel in registers: store loop is pure FMUL+STG.
    float wreg[NN];
    #pragma unroll
    for (int n = 0; n < NN; n++) wreg[n] = ws[n][cl];

    float* orow = out + ((size_t)(b * NN) * DD + c0 + cl) * SS + (s_base + sq);

    #pragma unroll
    for (int t = 0; t < NT; t++) {
        const int cur = t & 1;

        // Prefetch tile t+1: latency hides under the store burst below.
        if (t + 1 < NT) {
            p0 = *reinterpret_cast<const float4*>(
                qbase + (size_t)((t + 1) * STILE + sl0) * DD);
            p1 = *reinterpret_cast<const float4*>(
                qbase + (size_t)((t + 1) * STILE + sl0 + 32) * DD);
        }

        // Transposed gather (banks (sq+i+cl) mod 32 -> conflict-free).
        float4 v0, v1;
        v0.x = tile[cur][sq + 0][cl];
        v0.y = tile[cur][sq + 1][cl];
        v0.z = tile[cur][sq + 2][cl];
        v0.w = tile[cur][sq + 3][cl];
        v1.x = tile[cur][sq + 32][cl];
        v1.y = tile[cur][sq + 33][cl];
        v1.z = tile[cur][sq + 34][cl];
        v1.w = tile[cur][sq + 35][cl];

        // 40 independent streaming STG.128 per thread.
        float* op = orow + t * STILE;
        #pragma unroll
        for (int n = 0; n < NN; n++) {
            const float sc = wreg[n];
            float4 o0, o1;
            o0.x = v0.x * sc; o0.y = v0.y * sc; o0.z = v0.z * sc; o0.w = v0.w * sc;
            o1.x = v1.x * sc; o1.y = v1.y * sc; o1.z = v1.z * sc; o1.w = v1.w * sc;
            float* p = op + (size_t)n * DD * SS;
            __stcs(reinterpret_cast<float4*>(p), o0);
            __stcs(reinterpret_cast<float4*>(p + 32), o1);
        }

        // Stage prefetched tile into the other buffer; single barrier per iter.
        if (t + 1 < NT) {
            const int nxt = cur ^ 1;
            float* r0 = &tile[nxt][sl0][cq];
            r0[0] = p0.x; r0[1] = p0.y; r0[2] = p0.z; r0[3] = p0.w;
            float* r1 = &tile[nxt][sl0 + 32][cq];
            r1[0] = p1.x; r1[1] = p1.y; r1[2] = p1.z; r1[3] = p1.w;
            __syncthreads();
        }
    }
}

extern "C" void kernel_launch(void* const* d_in, const int* in_sizes, int n_in,
                              void* d_out, int out_size)
{
    const float* q = (const float*)d_in[0];   // (8, 2048, 256) fp32
    const float* w = (const float*)d_in[1];   // (20, 256) fp32
    float* out = (float*)d_out;               // (160, 256, 2048) fp32

    dim3 grid(SS / (STILE * NT), DD / 32, BB);   // (8, 8, 8) = 512 blocks
    FeatureReweightingModule_72447508349057_kernel<<<grid, 256>>>(q, w, out);
}

// round 10
// speedup vs baseline: 1.2083x; 1.2083x over previous
#include <cuda_runtime.h>

// out[(b*N+n)*D + c, s] = q[b, s, c] * w[n, c]
// q: (B=8, S=2048, D=256) fp32, c contiguous
// w: (N=20, D=256) fp32
// out: (B*N=160, D=256, S=2048) fp32, s contiguous
//
// R9 = R8 with the weight-staging bug fixed (NPB*32=320 > 256 threads, so
// staging must be a strided loop, not a single guarded store).
// Class-split blocks: each block handles 10 of 20 classes -> fewer regs,
// 8 CTAs/SM, 4096 blocks for smooth wave balance. q read twice (2nd from L2).

#define BB 8
#define SS 2048
#define DD 256
#define NN 20
#define STILE 64
#define NSPLIT 2
#define NPB (NN / NSPLIT)   // 10 classes per block

__global__ __launch_bounds__(256)
void FeatureReweightingModule_72447508349057_kernel(
    const float* __restrict__ q,
    const float* __restrict__ w,
    float* __restrict__ out)
{
    __shared__ float tile[STILE][33];   // [s_local][c_local], padded
    __shared__ float ws[NPB][32];       // weight slice for this (c-tile, n-half)

    const int s0 = blockIdx.x * STILE;      // 32 s-tiles
    const int c0 = blockIdx.y << 5;         // 8 c-tiles
    const int b  = blockIdx.z >> 1;         // 8 batches
    const int n0 = (blockIdx.z & 1) * NPB;  // class half: 0 or 10

    const int tid = threadIdx.x;            // 256 threads

    // Stage the 10x32 weight slice (320 elements, 256 threads -> strided loop).
    #pragma unroll
    for (int i = tid; i < NPB * 32; i += 256) {
        const int n = i >> 5;
        const int c = i & 31;
        ws[n][c] = w[(n0 + n) * DD + c0 + c];
    }

    // Load phase: 2 coalesced LDG.128 per thread along c.
    #pragma unroll
    for (int k = 0; k < 2; k++) {
        const int idx = tid + k * 256;
        const int sl  = idx >> 3;             // 0..63
        const int cq  = (idx & 7) << 2;       // 0,4,...,28
        const float4 v = *reinterpret_cast<const float4*>(
            &q[((size_t)b * SS + (s0 + sl)) * DD + c0 + cq]);
        tile[sl][cq + 0] = v.x;
        tile[sl][cq + 1] = v.y;
        tile[sl][cq + 2] = v.z;
        tile[sl][cq + 3] = v.w;
    }
    __syncthreads();

    // Transposed gather: two float4s of consecutive s for one c.
    // Banks (sq+i+cl) mod 32: all 32 distinct per warp -> conflict-free.
    const int cl = tid >> 3;                  // 0..31 (c within tile)
    const int sq = (tid & 7) << 2;            // 0,4,...,28
    float4 v0, v1;
    v0.x = tile[sq + 0][cl];
    v0.y = tile[sq + 1][cl];
    v0.z = tile[sq + 2][cl];
    v0.w = tile[sq + 3][cl];
    v1.x = tile[sq + 32][cl];
    v1.y = tile[sq + 33][cl];
    v1.z = tile[sq + 34][cl];
    v1.w = tile[sq + 35][cl];

    // Weights for this channel in registers: store loop is pure FMUL+STG.
    float wreg[NPB];
    #pragma unroll
    for (int n = 0; n < NPB; n++) wreg[n] = ws[n][cl];

    // Write phase: 20 independent streaming STG.128 per thread.
    float* orow = out + ((size_t)((b * NN + n0)) * DD + c0 + cl) * SS + (s0 + sq);
    #pragma unroll
    for (int n = 0; n < NPB; n++) {
        const float sc = wreg[n];
        float4 o0, o1;
        o0.x = v0.x * sc; o0.y = v0.y * sc; o0.z = v0.z * sc; o0.w = v0.w * sc;
        o1.x = v1.x * sc; o1.y = v1.y * sc; o1.z = v1.z * sc; o1.w = v1.w * sc;
        float* p = orow + (size_t)n * DD * SS;
        __stcs(reinterpret_cast<float4*>(p), o0);
        __stcs(reinterpret_cast<float4*>(p + 32), o1);
    }
}

extern "C" void kernel_launch(void* const* d_in, const int* in_sizes, int n_in,
                              void* d_out, int out_size)
{
    const float* q = (const float*)d_in[0];   // (8, 2048, 256) fp32
    const float* w = (const float*)d_in[1];   // (20, 256) fp32
    float* out = (float*)d_out;               // (160, 256, 2048) fp32

    dim3 grid(SS / STILE, DD / 32, BB * NSPLIT);   // (32, 8, 16) = 4096 blocks
    FeatureReweightingModule_72447508349057_kernel<<<grid, 256>>>(q, w, out);
}

// round 12
// speedup vs baseline: 1.2121x; 1.0031x over previous
#include <cuda_runtime.h>

// out[(b*N+n)*D + c, s] = q[b, s, c] * w[n, c]
// q: (B=8, S=2048, D=256) fp32, c contiguous
// w: (N=20, D=256) fp32
// out: (B*N=160, D=256, S=2048) fp32, s contiguous
//
// R10 = R9 with NSPLIT=4 (5 classes/block) + __launch_bounds__(256,8).
// Smaller reg footprint -> 8 CTAs/SM; 8192 blocks -> smooth wave balance.
// q read 4x but L2-resident (16.8MB << 126MB), so extra reads hit L2 only.

#define BB 8
#define SS 2048
#define DD 256
#define NN 20
#define STILE 64
#define NSPLIT 4
#define NPB (NN / NSPLIT)   // 5 classes per block

__global__ __launch_bounds__(256, 8)
void FeatureReweightingModule_72447508349057_kernel(
    const float* __restrict__ q,
    const float* __restrict__ w,
    float* __restrict__ out)
{
    __shared__ float tile[STILE][33];   // [s_local][c_local], padded
    __shared__ float ws[NPB][32];       // weight slice (5 x 32 = 160 elems)

    const int s0 = blockIdx.x * STILE;          // 32 s-tiles
    const int c0 = blockIdx.y << 5;             // 8 c-tiles
    const int b  = blockIdx.z >> 2;             // 8 batches
    const int n0 = (blockIdx.z & 3) * NPB;      // class quarter: 0,5,10,15

    const int tid = threadIdx.x;                // 256 threads

    // Stage the 5x32 weight slice (160 <= 256 threads: single guarded store).
    if (tid < NPB * 32) {
        const int n = tid >> 5;
        const int c = tid & 31;
        ws[n][c] = w[(n0 + n) * DD + c0 + c];
    }

    // Load phase: 2 coalesced LDG.128 per thread along c.
    #pragma unroll
    for (int k = 0; k < 2; k++) {
        const int idx = tid + k * 256;
        const int sl  = idx >> 3;             // 0..63
        const int cq  = (idx & 7) << 2;       // 0,4,...,28
        const float4 v = *reinterpret_cast<const float4*>(
            &q[((size_t)b * SS + (s0 + sl)) * DD + c0 + cq]);
        tile[sl][cq + 0] = v.x;
        tile[sl][cq + 1] = v.y;
        tile[sl][cq + 2] = v.z;
        tile[sl][cq + 3] = v.w;
    }
    __syncthreads();

    // Transposed gather: two float4s of consecutive s for one c.
    // Banks (sq+i+cl) mod 32: all 32 distinct per warp -> conflict-free.
    const int cl = tid >> 3;                  // 0..31 (c within tile)
    const int sq = (tid & 7) << 2;            // 0,4,...,28
    float4 v0, v1;
    v0.x = tile[sq + 0][cl];
    v0.y = tile[sq + 1][cl];
    v0.z = tile[sq + 2][cl];
    v0.w = tile[sq + 3][cl];
    v1.x = tile[sq + 32][cl];
    v1.y = tile[sq + 33][cl];
    v1.z = tile[sq + 34][cl];
    v1.w = tile[sq + 35][cl];

    // Weights for this channel in registers: store loop is pure FMUL+STG.
    float wreg[NPB];
    #pragma unroll
    for (int n = 0; n < NPB; n++) wreg[n] = ws[n][cl];

    // Write phase: 10 independent streaming STG.128 per thread.
    float* orow = out + ((size_t)((b * NN + n0)) * DD + c0 + cl) * SS + (s0 + sq);
    #pragma unroll
    for (int n = 0; n < NPB; n++) {
        const float sc = wreg[n];
        float4 o0, o1;
        o0.x = v0.x * sc; o0.y = v0.y * sc; o0.z = v0.z * sc; o0.w = v0.w * sc;
        o1.x = v1.x * sc; o1.y = v1.y * sc; o1.z = v1.z * sc; o1.w = v1.w * sc;
        float* p = orow + (size_t)n * DD * SS;
        __stcs(reinterpret_cast<float4*>(p), o0);
        __stcs(reinterpret_cast<float4*>(p + 32), o1);
    }
}

extern "C" void kernel_launch(void* const* d_in, const int* in_sizes, int n_in,
                              void* d_out, int out_size)
{
    const float* q = (const float*)d_in[0];   // (8, 2048, 256) fp32
    const float* w = (const float*)d_in[1];   // (20, 256) fp32
    float* out = (float*)d_out;               // (160, 256, 2048) fp32

    dim3 grid(SS / STILE, DD / 32, BB * NSPLIT);   // (32, 8, 32) = 8192 blocks
    FeatureReweightingModule_72447508349057_kernel<<<grid, 256>>>(q, w, out);
}